// round 3
// baseline (speedup 1.0000x reference)
#include <cuda_runtime.h>

typedef unsigned long long u64;

#define Bn 8
#define Cn 64
#define Hn 128
#define Wn 128
#define PLANE 16384
#define TW 32
#define TH 16
#define HH 18
#define HWD 34
#define CC 16

// Scratch (device globals: allocation-free per harness rules)
__device__ float g_S[Bn * PLANE];            // sum_c fu^2
__device__ float g_F[Bn * PLANE];            // sum_c fe^2
__device__ float g_X[2][Bn][9][PLANE];       // partial cross terms per channel group
__device__ float g_w[Bn][9][PLANE];          // softmax weights

__device__ __forceinline__ u64 pk(float a, float b) {
    u64 r; asm("mov.b64 %0, {%1, %2};" : "=l"(r) : "f"(a), "f"(b)); return r;
}
__device__ __forceinline__ float2 unpk(u64 v) {
    float2 r; asm("mov.b64 {%0, %1}, %2;" : "=f"(r.x), "=f"(r.y) : "l"(v)); return r;
}
__device__ __forceinline__ u64 fma2(u64 a, u64 b, u64 c) {
    u64 d; asm("fma.rn.f32x2 %0, %1, %2, %3;" : "=l"(d) : "l"(a), "l"(b), "l"(c)); return d;
}
__device__ __forceinline__ u64 add2(u64 a, u64 b) {
    u64 d; asm("add.rn.f32x2 %0, %1, %2;" : "=l"(d) : "l"(a), "l"(b)); return d;
}

// ---------------- K0: channelwise sum-of-squares maps ----------------
__global__ void __launch_bounds__(128) k0_kernel(const float* __restrict__ fe,
                                                 const float* __restrict__ fu) {
    int t = blockIdx.x * 128 + threadIdx.x;          // 32768 threads, one float4 each
    int b = t >> 12;                                  // PLANE/4 = 4096 per batch
    int q = t & 4095;
    const float4* fup = reinterpret_cast<const float4*>(fu) + (size_t)b * Cn * (PLANE / 4) + q;
    const float4* fep = reinterpret_cast<const float4*>(fe) + (size_t)b * Cn * (PLANE / 4) + q;
    float4 s = make_float4(0.f, 0.f, 0.f, 0.f);
    float4 f = make_float4(0.f, 0.f, 0.f, 0.f);
    #pragma unroll 4
    for (int c = 0; c < Cn; ++c) {
        float4 v = __ldg(fup + c * (PLANE / 4));
        s.x = fmaf(v.x, v.x, s.x); s.y = fmaf(v.y, v.y, s.y);
        s.z = fmaf(v.z, v.z, s.z); s.w = fmaf(v.w, v.w, s.w);
        float4 u = __ldg(fep + c * (PLANE / 4));
        f.x = fmaf(u.x, u.x, f.x); f.y = fmaf(u.y, u.y, f.y);
        f.z = fmaf(u.z, u.z, f.z); f.w = fmaf(u.w, u.w, f.w);
    }
    reinterpret_cast<float4*>(g_S)[t] = s;
    reinterpret_cast<float4*>(g_F)[t] = f;
}

// ---------------- shared halo loader (16 channels, zero-padded) ----------------
// 612 halo elems per channel; each of 128 threads owns fixed (lr,lc) slots.
__device__ __forceinline__ void load_halo(float* smf, const float* fub,
                                          int row0, int col0, int tid) {
    // Precompute the (up to 5) slot coordinates once.
    int idx[5], gofs[5];
    bool ok[5];
    int n = 0;
    #pragma unroll
    for (int t = 0; t < 5; ++t) {
        int i = tid + t * 128;
        if (i < HH * HWD) {
            int lr = i / HWD;
            int lc = i - lr * HWD;
            int gr = row0 - 1 + lr;
            int gc = col0 - 1 + lc;
            idx[n] = i;
            ok[n] = ((unsigned)gr < Hn) && ((unsigned)gc < Wn);
            gofs[n] = gr * Wn + gc;
            ++n;
        }
    }
    for (int c = 0; c < CC; ++c) {
        const float* src = fub + c * PLANE;
        float* dst = smf + c * (HH * HWD);
        #pragma unroll
        for (int t = 0; t < 5; ++t) {
            if (t < n) {
                float v = ok[t] ? __ldg(src + gofs[t]) : 0.f;
                dst[idx[t]] = v;
            }
        }
    }
}

// ---------------- K1: cross terms X_k = sum_c fe*patch (per channel group) ----------------
__global__ void __launch_bounds__(128, 5)
k1_kernel(const float* __restrict__ fe, const float* __restrict__ fu) {
    __shared__ float sm[CC * HH * HWD];
    const int tx = threadIdx.x, ty = threadIdx.y;
    const int tid = ty * 16 + tx;
    const int col0 = blockIdx.x * TW, row0 = blockIdx.y * TH;
    const int b = blockIdx.z >> 1, cg = blockIdx.z & 1;
    const int r = row0 + 2 * ty;   // pixel rows r, r+1
    const int x = col0 + 2 * tx;   // pixel cols x, x+1

    u64 X2[2][9];
    #pragma unroll
    for (int p = 0; p < 2; ++p)
        #pragma unroll
        for (int k = 0; k < 9; ++k) X2[p][k] = 0ull;

    const float* feb = fe + (size_t)b * Cn * PLANE + r * Wn + x;

    for (int ch = 0; ch < 2; ++ch) {
        const int cbase = cg * 32 + ch * CC;
        load_halo(sm, fu + ((size_t)b * Cn + cbase) * PLANE, row0, col0, tid);
        __syncthreads();
        #pragma unroll 4
        for (int c = 0; c < CC; ++c) {
            float2 fA = *reinterpret_cast<const float2*>(feb + (size_t)(cbase + c) * PLANE);
            float2 fB = *reinterpret_cast<const float2*>(feb + (size_t)(cbase + c) * PLANE + Wn);
            u64 feA = pk(fA.x, fA.y), feB = pk(fB.x, fB.y);
            u64 av[4], mv[4], cv[4];
            #pragma unroll
            for (int wr = 0; wr < 4; ++wr) {
                const float* rp = sm + c * (HH * HWD) + (2 * ty + wr) * HWD + 2 * tx;
                float2 v01 = *reinterpret_cast<const float2*>(rp);
                float2 v23 = *reinterpret_cast<const float2*>(rp + 2);
                av[wr] = pk(v01.x, v01.y);
                mv[wr] = pk(v01.y, v23.x);
                cv[wr] = pk(v23.x, v23.y);
            }
            #pragma unroll
            for (int j = 0; j < 3; ++j) {
                X2[0][3 * j + 0] = fma2(av[j], feA, X2[0][3 * j + 0]);
                X2[0][3 * j + 1] = fma2(mv[j], feA, X2[0][3 * j + 1]);
                X2[0][3 * j + 2] = fma2(cv[j], feA, X2[0][3 * j + 2]);
                X2[1][3 * j + 0] = fma2(av[j + 1], feB, X2[1][3 * j + 0]);
                X2[1][3 * j + 1] = fma2(mv[j + 1], feB, X2[1][3 * j + 1]);
                X2[1][3 * j + 2] = fma2(cv[j + 1], feB, X2[1][3 * j + 2]);
            }
        }
        __syncthreads();
    }

    const int hw0 = r * Wn + x;
    #pragma unroll
    for (int k = 0; k < 9; ++k) {
        *reinterpret_cast<float2*>(&g_X[cg][b][k][hw0])      = unpk(X2[0][k]);
        *reinterpret_cast<float2*>(&g_X[cg][b][k][hw0 + Wn]) = unpk(X2[1][k]);
    }
}

// ---------------- K2: distances + softmax -> weights ----------------
__global__ void __launch_bounds__(256) k2_kernel() {
    int t = blockIdx.x * 256 + threadIdx.x;     // 131072 threads, one pixel each
    int b = t >> 14;
    int hw = t & (PLANE - 1);
    int rr = hw >> 7, cx = hw & 127;
    float F = g_F[t];
    float dist[9];
    float mn = 3.402823e38f;
    #pragma unroll
    for (int k = 0; k < 9; ++k) {
        int nr = rr + k / 3 - 1;
        int nc = cx + (k % 3) - 1;
        float S = 0.f;
        if ((unsigned)nr < (unsigned)Hn && (unsigned)nc < (unsigned)Wn)
            S = __ldg(&g_S[(b << 14) + nr * Wn + nc]);
        float X = g_X[0][b][k][hw] + g_X[1][b][k][hw];
        float d2 = fmaxf(fmaf(-2.f, X, S + F), 0.f);
        dist[k] = sqrtf(d2);
        mn = fminf(mn, dist[k]);
    }
    float wv[9], s = 0.f;
    #pragma unroll
    for (int k = 0; k < 9; ++k) { wv[k] = __expf(mn - dist[k]); s += wv[k]; }
    float inv = 1.f / s;
    #pragma unroll
    for (int k = 0; k < 9; ++k) g_w[b][k][hw] = wv[k] * inv;
}

// ---------------- K3: weighted neighbor sum + fe ----------------
__global__ void __launch_bounds__(128, 5)
k3_kernel(const float* __restrict__ fe, const float* __restrict__ fu,
          float* __restrict__ out) {
    __shared__ float sm[CC * HH * HWD];
    const int tx = threadIdx.x, ty = threadIdx.y;
    const int tid = ty * 16 + tx;
    const int col0 = blockIdx.x * TW, row0 = blockIdx.y * TH;
    const int b = blockIdx.z >> 1, cg = blockIdx.z & 1;
    const int r = row0 + 2 * ty;
    const int x = col0 + 2 * tx;
    const int hw0 = r * Wn + x;

    u64 w2[2][9];
    #pragma unroll
    for (int k = 0; k < 9; ++k) {
        float2 wa = *reinterpret_cast<const float2*>(&g_w[b][k][hw0]);
        float2 wb = *reinterpret_cast<const float2*>(&g_w[b][k][hw0 + Wn]);
        w2[0][k] = pk(wa.x, wa.y);
        w2[1][k] = pk(wb.x, wb.y);
    }

    const float* feb = fe + (size_t)b * Cn * PLANE + hw0;
    float* ob = out + (size_t)b * Cn * PLANE + hw0;

    for (int ch = 0; ch < 2; ++ch) {
        const int cbase = cg * 32 + ch * CC;
        load_halo(sm, fu + ((size_t)b * Cn + cbase) * PLANE, row0, col0, tid);
        __syncthreads();
        #pragma unroll 4
        for (int c = 0; c < CC; ++c) {
            u64 av[4], mv[4], cv[4];
            #pragma unroll
            for (int wr = 0; wr < 4; ++wr) {
                const float* rp = sm + c * (HH * HWD) + (2 * ty + wr) * HWD + 2 * tx;
                float2 v01 = *reinterpret_cast<const float2*>(rp);
                float2 v23 = *reinterpret_cast<const float2*>(rp + 2);
                av[wr] = pk(v01.x, v01.y);
                mv[wr] = pk(v01.y, v23.x);
                cv[wr] = pk(v23.x, v23.y);
            }
            u64 acc0 = 0ull, acc1 = 0ull;
            #pragma unroll
            for (int j = 0; j < 3; ++j) {
                acc0 = fma2(av[j], w2[0][3 * j + 0], acc0);
                acc0 = fma2(mv[j], w2[0][3 * j + 1], acc0);
                acc0 = fma2(cv[j], w2[0][3 * j + 2], acc0);
                acc1 = fma2(av[j + 1], w2[1][3 * j + 0], acc1);
                acc1 = fma2(mv[j + 1], w2[1][3 * j + 1], acc1);
                acc1 = fma2(cv[j + 1], w2[1][3 * j + 2], acc1);
            }
            float2 fA = *reinterpret_cast<const float2*>(feb + (size_t)(cbase + c) * PLANE);
            float2 fB = *reinterpret_cast<const float2*>(feb + (size_t)(cbase + c) * PLANE + Wn);
            acc0 = add2(acc0, pk(fA.x, fA.y));
            acc1 = add2(acc1, pk(fB.x, fB.y));
            *reinterpret_cast<float2*>(ob + (size_t)(cbase + c) * PLANE)      = unpk(acc0);
            *reinterpret_cast<float2*>(ob + (size_t)(cbase + c) * PLANE + Wn) = unpk(acc1);
        }
        __syncthreads();
    }
}

extern "C" void kernel_launch(void* const* d_in, const int* in_sizes, int n_in,
                              void* d_out, int out_size) {
    const float* fe = (const float*)d_in[0];   // fe_lv
    const float* fu = (const float*)d_in[1];   // fused_features
    float* out = (float*)d_out;

    k0_kernel<<<256, 128>>>(fe, fu);

    dim3 blk(16, 8);
    dim3 grd(Wn / TW, Hn / TH, Bn * 2);        // (4, 8, 16) = 512 blocks
    k1_kernel<<<grd, blk>>>(fe, fu);

    k2_kernel<<<(Bn * PLANE) / 256, 256>>>();

    k3_kernel<<<grd, blk>>>(fe, fu, out);
}

// round 4
// speedup vs baseline: 3.6489x; 3.6489x over previous
#include <cuda_runtime.h>

typedef unsigned long long u64;

#define Bn 8
#define Cn 64
#define Hn 128
#define Wn 128
#define PLANE (Hn * Wn)
#define NACC 26   // 18 X + 6 S + 2 F  (u64 each)
#define NPAD 27

__device__ __forceinline__ u64 pk(float a, float b) {
    u64 r; asm("mov.b64 %0, {%1, %2};" : "=l"(r) : "f"(a), "f"(b)); return r;
}
__device__ __forceinline__ void unpk(u64 v, float& a, float& b) {
    asm("mov.b64 {%0, %1}, %2;" : "=f"(a), "=f"(b) : "l"(v));
}
__device__ __forceinline__ u64 fma2(u64 a, u64 b, u64 c) {
    u64 d; asm("fma.rn.f32x2 %0, %1, %2, %3;" : "=l"(d) : "l"(a), "l"(b), "l"(c)); return d;
}
__device__ __forceinline__ u64 add2(u64 a, u64 b) {
    u64 d; asm("add.rn.f32x2 %0, %1, %2;" : "=l"(d) : "l"(a), "l"(b)); return d;
}

__global__ void __launch_bounds__(128)
fused_kernel(const float* __restrict__ fe, const float* __restrict__ fu,
             float* __restrict__ out) {
    __shared__ u64 red[4][32][NPAD];

    const int tid = threadIdx.x;
    const int w = tid >> 5, l = tid & 31;
    const int b = blockIdx.x >> 7;       // 1024 blocks = 8 batches x 128 rows
    const int r = blockIdx.x & 127;
    const int x0 = l * 4;
    const int c0 = w * 16;
    const bool pm = (r > 0), pp = (r < Hn - 1);

    const size_t base = ((size_t)b * Cn + c0) * PLANE + (size_t)r * Wn + x0;
    const float* fup = fu + base;
    const float* fep = fe + base;

    // ---------------- Phase 1: accumulate X (9 cross terms), S (3 rows), F ----------------
    u64 X2[9][2], S2[3][2], F2[2];
    #pragma unroll
    for (int k = 0; k < 9; ++k) { X2[k][0] = 0ull; X2[k][1] = 0ull; }
    #pragma unroll
    for (int d = 0; d < 3; ++d) { S2[d][0] = 0ull; S2[d][1] = 0ull; }
    F2[0] = 0ull; F2[1] = 0ull;

    const float4 z4 = make_float4(0.f, 0.f, 0.f, 0.f);

    #pragma unroll 4
    for (int c = 0; c < 16; ++c) {
        const float* uc = fup + c * PLANE;
        float4 vr[3];
        vr[0] = pm ? __ldg((const float4*)(uc - Wn)) : z4;
        vr[1] = __ldg((const float4*)uc);
        vr[2] = pp ? __ldg((const float4*)(uc + Wn)) : z4;
        float4 f4 = __ldg((const float4*)(fep + c * PLANE));

        u64 fe01 = pk(f4.x, f4.y), fe23 = pk(f4.z, f4.w);
        F2[0] = fma2(fe01, fe01, F2[0]);
        F2[1] = fma2(fe23, fe23, F2[1]);

        #pragma unroll
        for (int dr = 0; dr < 3; ++dr) {
            float4 v = vr[dr];
            float L = __shfl_up_sync(0xffffffffu, v.w, 1);  if (l == 0)  L = 0.f;
            float R = __shfl_down_sync(0xffffffffu, v.x, 1); if (l == 31) R = 0.f;
            u64 c01 = pk(v.x, v.y), c23 = pk(v.z, v.w);
            u64 l01 = pk(L, v.x),   yz  = pk(v.y, v.z), r23 = pk(v.w, R);

            S2[dr][0] = fma2(c01, c01, S2[dr][0]);
            S2[dr][1] = fma2(c23, c23, S2[dr][1]);

            X2[dr*3+0][0] = fma2(l01, fe01, X2[dr*3+0][0]);
            X2[dr*3+0][1] = fma2(yz,  fe23, X2[dr*3+0][1]);
            X2[dr*3+1][0] = fma2(c01, fe01, X2[dr*3+1][0]);
            X2[dr*3+1][1] = fma2(c23, fe23, X2[dr*3+1][1]);
            X2[dr*3+2][0] = fma2(yz,  fe01, X2[dr*3+2][0]);
            X2[dr*3+2][1] = fma2(r23, fe23, X2[dr*3+2][1]);
        }
    }

    // ---------------- Cross-warp reduction (sum the 4 channel groups) ----------------
    {
        u64* slot = red[w][l];
        #pragma unroll
        for (int k = 0; k < 9; ++k) { slot[2*k] = X2[k][0]; slot[2*k+1] = X2[k][1]; }
        #pragma unroll
        for (int d = 0; d < 3; ++d) { slot[18+2*d] = S2[d][0]; slot[19+2*d] = S2[d][1]; }
        slot[24] = F2[0]; slot[25] = F2[1];
    }
    __syncthreads();
    {
        #pragma unroll
        for (int k = 0; k < 9; ++k) {
            X2[k][0] = add2(add2(red[0][l][2*k],   red[1][l][2*k]),
                            add2(red[2][l][2*k],   red[3][l][2*k]));
            X2[k][1] = add2(add2(red[0][l][2*k+1], red[1][l][2*k+1]),
                            add2(red[2][l][2*k+1], red[3][l][2*k+1]));
        }
        #pragma unroll
        for (int d = 0; d < 3; ++d) {
            S2[d][0] = add2(add2(red[0][l][18+2*d], red[1][l][18+2*d]),
                            add2(red[2][l][18+2*d], red[3][l][18+2*d]));
            S2[d][1] = add2(add2(red[0][l][19+2*d], red[1][l][19+2*d]),
                            add2(red[2][l][19+2*d], red[3][l][19+2*d]));
        }
        F2[0] = add2(add2(red[0][l][24], red[1][l][24]),
                     add2(red[2][l][24], red[3][l][24]));
        F2[1] = add2(add2(red[0][l][25], red[1][l][25]),
                     add2(red[2][l][25], red[3][l][25]));
    }

    // ---------------- Phase 2: distances + softmax -> packed weights ----------------
    float Xs[9][4], Ss[3][6], Fs[4];   // Ss[dr] = {L, s0, s1, s2, s3, R}
    #pragma unroll
    for (int k = 0; k < 9; ++k) {
        unpk(X2[k][0], Xs[k][0], Xs[k][1]);
        unpk(X2[k][1], Xs[k][2], Xs[k][3]);
    }
    #pragma unroll
    for (int d = 0; d < 3; ++d) {
        unpk(S2[d][0], Ss[d][1], Ss[d][2]);
        unpk(S2[d][1], Ss[d][3], Ss[d][4]);
        float SL = __shfl_up_sync(0xffffffffu, Ss[d][4], 1);  if (l == 0)  SL = 0.f;
        float SR = __shfl_down_sync(0xffffffffu, Ss[d][1], 1); if (l == 31) SR = 0.f;
        Ss[d][0] = SL; Ss[d][5] = SR;
    }
    unpk(F2[0], Fs[0], Fs[1]);
    unpk(F2[1], Fs[2], Fs[3]);

    u64 w2[9][2];
    float wtmp[9][4];
    #pragma unroll
    for (int p = 0; p < 4; ++p) {
        float F = Fs[p];
        float dist[9];
        float mn = 3.402823e38f;
        #pragma unroll
        for (int dr = 0; dr < 3; ++dr) {
            #pragma unroll
            for (int dc = 0; dc < 3; ++dc) {
                float Sv = Ss[dr][p + dc];           // p+dc in [0,5]
                float d2 = fmaf(-2.f, Xs[dr*3+dc][p], Sv + F);
                float dd = sqrtf(fmaxf(d2, 0.f));
                dist[dr*3+dc] = dd;
                mn = fminf(mn, dd);
            }
        }
        float s = 0.f;
        #pragma unroll
        for (int k = 0; k < 9; ++k) { float e = __expf(mn - dist[k]); wtmp[k][p] = e; s += e; }
        float inv = 1.f / s;
        #pragma unroll
        for (int k = 0; k < 9; ++k) wtmp[k][p] *= inv;
    }
    #pragma unroll
    for (int k = 0; k < 9; ++k) {
        w2[k][0] = pk(wtmp[k][0], wtmp[k][1]);
        w2[k][1] = pk(wtmp[k][2], wtmp[k][3]);
    }

    // ---------------- Phase 3: weighted neighbor sum + fe -> out ----------------
    float* op = out + base;
    #pragma unroll 2
    for (int c = 0; c < 16; ++c) {
        const float* uc = fup + c * PLANE;
        float4 vr[3];
        vr[0] = pm ? __ldg((const float4*)(uc - Wn)) : z4;
        vr[1] = __ldg((const float4*)uc);
        vr[2] = pp ? __ldg((const float4*)(uc + Wn)) : z4;
        float4 f4 = __ldg((const float4*)(fep + c * PLANE));

        u64 acc0 = pk(f4.x, f4.y);
        u64 acc1 = pk(f4.z, f4.w);
        #pragma unroll
        for (int dr = 0; dr < 3; ++dr) {
            float4 v = vr[dr];
            float L = __shfl_up_sync(0xffffffffu, v.w, 1);  if (l == 0)  L = 0.f;
            float R = __shfl_down_sync(0xffffffffu, v.x, 1); if (l == 31) R = 0.f;
            u64 c01 = pk(v.x, v.y), c23 = pk(v.z, v.w);
            u64 l01 = pk(L, v.x),   yz  = pk(v.y, v.z), r23 = pk(v.w, R);

            acc0 = fma2(l01, w2[dr*3+0][0], acc0);
            acc1 = fma2(yz,  w2[dr*3+0][1], acc1);
            acc0 = fma2(c01, w2[dr*3+1][0], acc0);
            acc1 = fma2(c23, w2[dr*3+1][1], acc1);
            acc0 = fma2(yz,  w2[dr*3+2][0], acc0);
            acc1 = fma2(r23, w2[dr*3+2][1], acc1);
        }
        float4 o4;
        unpk(acc0, o4.x, o4.y);
        unpk(acc1, o4.z, o4.w);
        *(float4*)(op + c * PLANE) = o4;
    }
}

extern "C" void kernel_launch(void* const* d_in, const int* in_sizes, int n_in,
                              void* d_out, int out_size) {
    const float* fe = (const float*)d_in[0];   // fe_lv
    const float* fu = (const float*)d_in[1];   // fused_features
    float* out = (float*)d_out;

    fused_kernel<<<Bn * Hn, 128>>>(fe, fu, out);   // 1024 blocks x 128 threads
}